// round 2
// baseline (speedup 1.0000x reference)
#include <cuda_runtime.h>
#include <math.h>

// Problem constants (shapes are fixed for this problem instance)
#define EE 400000
#define NN 50000
#define RR 6
#define HH 128
#define DD 256
#define LL 3

// Scratch (device globals — no allocation allowed in kernel_launch)
__device__ float g_h [(size_t)EE * HH];   // [E,128]
__device__ float g_t0[(size_t)EE * DD];   // [E,256]
__device__ float g_t1[(size_t)EE * DD];   // [E,256]

// ---------------- packed f32x2 helpers (Blackwell) ----------------
__device__ __forceinline__ unsigned long long pk2(float lo, float hi) {
    unsigned long long r;
    asm("mov.b64 %0, {%1, %2};" : "=l"(r) : "f"(lo), "f"(hi));
    return r;
}
__device__ __forceinline__ void fma2(unsigned long long& d,
                                     unsigned long long a,
                                     unsigned long long b) {
    asm("fma.rn.f32x2 %0, %1, %2, %0;" : "+l"(d) : "l"(a), "l"(b));
}
__device__ __forceinline__ float2 up2(unsigned long long v) {
    float2 f;
    asm("mov.b64 {%0, %1}, %2;" : "=f"(f.x), "=f"(f.y) : "l"(v));
    return f;
}

// ---------------- zero x_spe region of d_out ----------------
__global__ void zero_kernel(float4* p, int n4) {
    int i = blockIdx.x * blockDim.x + threadIdx.x;
    if (i < n4) p[i] = make_float4(0.f, 0.f, 0.f, 0.f);
}

// ---------------- h = (rbf @ w_rbf) * x ; scatter-add into x_spe ----------------
// one warp per edge, lane handles 4 consecutive channels
__global__ void h_scatter_kernel(const float* __restrict__ x,
                                 const float* __restrict__ rbf,
                                 const int*   __restrict__ idx,
                                 const float* __restrict__ w_rbf,
                                 float* __restrict__ xspe,
                                 float* __restrict__ gh,
                                 int E) {
    int gw = (blockIdx.x * blockDim.x + threadIdx.x) >> 5;
    if (gw >= E) return;
    int lane = threadIdx.x & 31;
    int c = lane * 4;

    const float* rb = rbf + (size_t)gw * RR;
    float r0 = __ldg(rb + 0), r1 = __ldg(rb + 1), r2 = __ldg(rb + 2);
    float r3 = __ldg(rb + 3), r4 = __ldg(rb + 4), r5 = __ldg(rb + 5);
    int node = __ldg(idx + gw);

    float4 xv = *reinterpret_cast<const float4*>(x + (size_t)gw * HH + c);
    float4 w0 = *reinterpret_cast<const float4*>(w_rbf + 0 * HH + c);
    float4 w1 = *reinterpret_cast<const float4*>(w_rbf + 1 * HH + c);
    float4 w2 = *reinterpret_cast<const float4*>(w_rbf + 2 * HH + c);
    float4 w3 = *reinterpret_cast<const float4*>(w_rbf + 3 * HH + c);
    float4 w4 = *reinterpret_cast<const float4*>(w_rbf + 4 * HH + c);
    float4 w5 = *reinterpret_cast<const float4*>(w_rbf + 5 * HH + c);

    float4 h;
    h.x = (r0*w0.x + r1*w1.x + r2*w2.x + r3*w3.x + r4*w4.x + r5*w5.x) * xv.x;
    h.y = (r0*w0.y + r1*w1.y + r2*w2.y + r3*w3.y + r4*w4.y + r5*w5.y) * xv.y;
    h.z = (r0*w0.z + r1*w1.z + r2*w2.z + r3*w3.z + r4*w4.z + r5*w5.z) * xv.z;
    h.w = (r0*w0.w + r1*w1.w + r2*w2.w + r3*w3.w + r4*w4.w + r5*w5.w) * xv.w;

    *reinterpret_cast<float4*>(gh + (size_t)gw * HH + c) = h;

    float* dst = xspe + (size_t)node * HH + c;
    atomicAdd(dst + 0, h.x);
    atomicAdd(dst + 1, h.y);
    atomicAdd(dst + 2, h.z);
    atomicAdd(dst + 3, h.w);
}

// ---------------- SGEMM with optional bias+silu epilogue ----------------
// C[M,256] = epi(A[M,K] @ B[K,256] + bias), tile 128x64, 256 threads,
// each thread 8 rows x 4 cols, inner loop uses packed fma.rn.f32x2.
template <int K, bool ACT>
__global__ __launch_bounds__(256)
void gemm_kernel(const float* __restrict__ A,
                 const float* __restrict__ B,
                 const float* __restrict__ bias,
                 float* __restrict__ C) {
    constexpr int BM = 128, BN = 64, BK = 16;
    __shared__ float As[BK][BM + 4];   // +4 pad: conflict-free transposed stores
    __shared__ float Bs[BK][BN];

    const int tid = threadIdx.x;
    const int tx = tid & 15;          // 16 col groups (4 cols each)
    const int ty = tid >> 4;          // 16 row groups (8 rows each)

    const float* Ab = A + (size_t)blockIdx.x * BM * K;
    const float* Bb = B + blockIdx.y * BN;

    unsigned long long acc[4][4];     // [row-pair][col], each holds 2 rows
#pragma unroll
    for (int i = 0; i < 4; i++)
#pragma unroll
        for (int j = 0; j < 4; j++) acc[i][j] = 0ull;

    for (int k0 = 0; k0 < K; k0 += BK) {
        // load A tile 128x16 (512 float4), store transposed
#pragma unroll
        for (int it = 0; it < 2; it++) {
            int q = tid + it * 256;
            int row = q >> 2;
            int c4 = (q & 3) * 4;
            float4 v = *reinterpret_cast<const float4*>(Ab + (size_t)row * K + k0 + c4);
            As[c4 + 0][row] = v.x;
            As[c4 + 1][row] = v.y;
            As[c4 + 2][row] = v.z;
            As[c4 + 3][row] = v.w;
        }
        // load B tile 16x64 (256 float4)
        {
            int row = tid >> 4;
            int c4 = (tid & 15) * 4;
            *reinterpret_cast<float4*>(&Bs[row][c4]) =
                *reinterpret_cast<const float4*>(Bb + (size_t)(k0 + row) * DD + c4);
        }
        __syncthreads();

#pragma unroll
        for (int k = 0; k < BK; k++) {
            // 8 A rows as 4 packed pairs (16B-aligned: (k*(BM+4)+ty*8)*4 is /16)
            ulonglong2 a01 = *reinterpret_cast<const ulonglong2*>(&As[k][ty * 8]);
            ulonglong2 a23 = *reinterpret_cast<const ulonglong2*>(&As[k][ty * 8 + 4]);
            float4 b = *reinterpret_cast<const float4*>(&Bs[k][tx * 4]);
            unsigned long long bb[4] = { pk2(b.x, b.x), pk2(b.y, b.y),
                                         pk2(b.z, b.z), pk2(b.w, b.w) };
#pragma unroll
            for (int j = 0; j < 4; j++) {
                fma2(acc[0][j], a01.x, bb[j]);
                fma2(acc[1][j], a01.y, bb[j]);
                fma2(acc[2][j], a23.x, bb[j]);
                fma2(acc[3][j], a23.y, bb[j]);
            }
        }
        __syncthreads();
    }

    // epilogue
    const int col0 = blockIdx.y * BN + tx * 4;
    float bv[4] = {0.f, 0.f, 0.f, 0.f};
    if (ACT) {
#pragma unroll
        for (int j = 0; j < 4; j++) bv[j] = __ldg(bias + col0 + j);
    }
    float ov[8][4];
#pragma unroll
    for (int rp = 0; rp < 4; rp++)
#pragma unroll
        for (int j = 0; j < 4; j++) {
            float2 f = up2(acc[rp][j]);
            ov[2 * rp + 0][j] = f.x;
            ov[2 * rp + 1][j] = f.y;
        }
#pragma unroll
    for (int r = 0; r < 8; r++) {
        size_t row = (size_t)blockIdx.x * BM + ty * 8 + r;
        float4 o;
        o.x = ov[r][0]; o.y = ov[r][1]; o.z = ov[r][2]; o.w = ov[r][3];
        if (ACT) {
            o.x += bv[0]; o.y += bv[1]; o.z += bv[2]; o.w += bv[3];
            o.x = o.x / (1.f + expf(-o.x));
            o.y = o.y / (1.f + expf(-o.y));
            o.z = o.z / (1.f + expf(-o.z));
            o.w = o.w / (1.f + expf(-o.w));
        }
        *reinterpret_cast<float4*>(C + row * DD + col0) = o;
    }
}

// ---------------- out = t @ w_out  (one warp per edge, D=256 dot) ----------------
__global__ void out_proj_kernel(const float* __restrict__ t,
                                const float* __restrict__ w_out,
                                float* __restrict__ out, int E) {
    int gw = (blockIdx.x * blockDim.x + threadIdx.x) >> 5;
    if (gw >= E) return;
    int lane = threadIdx.x & 31;
    const float4* tr = reinterpret_cast<const float4*>(t + (size_t)gw * DD);
    const float4* w = reinterpret_cast<const float4*>(w_out);
    float s = 0.f;
#pragma unroll
    for (int q = 0; q < 2; q++) {
        float4 a = tr[lane + 32 * q];
        float4 b = __ldg(&w[lane + 32 * q]);
        s += a.x * b.x + a.y * b.y + a.z * b.z + a.w * b.w;
    }
#pragma unroll
    for (int o = 16; o; o >>= 1) s += __shfl_xor_sync(0xffffffffu, s, o);
    if (lane == 0) out[gw] = s;
}

extern "C" void kernel_launch(void* const* d_in, const int* in_sizes, int n_in,
                              void* d_out, int out_size) {
    const float* x     = (const float*)d_in[0];   // [E,128]
    const float* rbf   = (const float*)d_in[1];   // [E,6]
    const int*   idx   = (const int*)  d_in[2];   // [E]
    const float* w_rbf = (const float*)d_in[3];   // [6,128]
    const float* w_up  = (const float*)d_in[4];   // [128,256]
    const float* Ws    = (const float*)d_in[5];   // [3,256,256]
    const float* bs    = (const float*)d_in[6];   // [3,256]
    const float* w_out = (const float*)d_in[7];   // [256,1]

    const int E = in_sizes[2];                    // 400000

    float* out_f = (float*)d_out;
    float* xspe  = out_f;                         // [N,128]
    float* out1  = out_f + (size_t)NN * HH;       // [E]

    float *ph, *pt0, *pt1;
    cudaGetSymbolAddress((void**)&ph,  g_h);
    cudaGetSymbolAddress((void**)&pt0, g_t0);
    cudaGetSymbolAddress((void**)&pt1, g_t1);

    // 1) zero x_spe
    {
        int n4 = (NN * HH) / 4;
        zero_kernel<<<(n4 + 255) / 256, 256>>>((float4*)xspe, n4);
    }
    // 2) h = (rbf@w_rbf)*x, scatter-add, stash h
    {
        int warps = E;
        int blocks = (warps * 32 + 255) / 256;
        h_scatter_kernel<<<blocks, 256>>>(x, rbf, idx, w_rbf, xspe, ph, E);
    }
    // 3) t0 = h @ w_up
    {
        dim3 grid(E / 128, DD / 64);
        gemm_kernel<HH, false><<<grid, 256>>>(ph, w_up, nullptr, pt0);
    }
    // 4) three silu(t@W + b) layers, ping-pong t0/t1
    {
        dim3 grid(E / 128, DD / 64);
        gemm_kernel<DD, true><<<grid, 256>>>(pt0, Ws + 0 * DD * DD, bs + 0 * DD, pt1);
        gemm_kernel<DD, true><<<grid, 256>>>(pt1, Ws + 1 * DD * DD, bs + 1 * DD, pt0);
        gemm_kernel<DD, true><<<grid, 256>>>(pt0, Ws + 2 * DD * DD, bs + 2 * DD, pt1);
    }
    // 5) out = t @ w_out
    {
        int blocks = (E * 32 + 255) / 256;
        out_proj_kernel<<<blocks, 256>>>(pt1, w_out, out1, E);
    }
}

// round 3
// speedup vs baseline: 1.0005x; 1.0005x over previous
#include <cuda_runtime.h>
#include <math.h>

// Problem constants (shapes are fixed for this problem instance)
#define EE 400000
#define NN 50000
#define RR 6
#define HH 128
#define DD 256
#define LL 3

// Scratch (device globals — no allocation allowed in kernel_launch)
__device__ float g_h [(size_t)EE * HH];   // [E,128]
__device__ float g_t0[(size_t)EE * DD];   // [E,256]
__device__ float g_t1[(size_t)EE * DD];   // [E,256]

// ---------------- packed f32x2 helpers (Blackwell) ----------------
__device__ __forceinline__ unsigned long long pk2(float lo, float hi) {
    unsigned long long r;
    asm("mov.b64 %0, {%1, %2};" : "=l"(r) : "f"(lo), "f"(hi));
    return r;
}
__device__ __forceinline__ void fma2(unsigned long long& d,
                                     unsigned long long a,
                                     unsigned long long b) {
    asm("fma.rn.f32x2 %0, %1, %2, %0;" : "+l"(d) : "l"(a), "l"(b));
}
__device__ __forceinline__ float2 up2(unsigned long long v) {
    float2 f;
    asm("mov.b64 {%0, %1}, %2;" : "=f"(f.x), "=f"(f.y) : "l"(v));
    return f;
}

// ---------------- zero x_spe region of d_out ----------------
__global__ void zero_kernel(float4* p, int n4) {
    int i = blockIdx.x * blockDim.x + threadIdx.x;
    if (i < n4) p[i] = make_float4(0.f, 0.f, 0.f, 0.f);
}

// ---------------- h = (rbf @ w_rbf) * x ; scatter-add into x_spe ----------------
// one warp per edge, lane handles 4 consecutive channels
__global__ void h_scatter_kernel(const float* __restrict__ x,
                                 const float* __restrict__ rbf,
                                 const int*   __restrict__ idx,
                                 const float* __restrict__ w_rbf,
                                 float* __restrict__ xspe,
                                 float* __restrict__ gh,
                                 int E) {
    int gw = (blockIdx.x * blockDim.x + threadIdx.x) >> 5;
    if (gw >= E) return;
    int lane = threadIdx.x & 31;
    int c = lane * 4;

    const float* rb = rbf + (size_t)gw * RR;
    float r0 = __ldg(rb + 0), r1 = __ldg(rb + 1), r2 = __ldg(rb + 2);
    float r3 = __ldg(rb + 3), r4 = __ldg(rb + 4), r5 = __ldg(rb + 5);
    int node = __ldg(idx + gw);

    float4 xv = *reinterpret_cast<const float4*>(x + (size_t)gw * HH + c);
    float4 w0 = *reinterpret_cast<const float4*>(w_rbf + 0 * HH + c);
    float4 w1 = *reinterpret_cast<const float4*>(w_rbf + 1 * HH + c);
    float4 w2 = *reinterpret_cast<const float4*>(w_rbf + 2 * HH + c);
    float4 w3 = *reinterpret_cast<const float4*>(w_rbf + 3 * HH + c);
    float4 w4 = *reinterpret_cast<const float4*>(w_rbf + 4 * HH + c);
    float4 w5 = *reinterpret_cast<const float4*>(w_rbf + 5 * HH + c);

    float4 h;
    h.x = (r0*w0.x + r1*w1.x + r2*w2.x + r3*w3.x + r4*w4.x + r5*w5.x) * xv.x;
    h.y = (r0*w0.y + r1*w1.y + r2*w2.y + r3*w3.y + r4*w4.y + r5*w5.y) * xv.y;
    h.z = (r0*w0.z + r1*w1.z + r2*w2.z + r3*w3.z + r4*w4.z + r5*w5.z) * xv.z;
    h.w = (r0*w0.w + r1*w1.w + r2*w2.w + r3*w3.w + r4*w4.w + r5*w5.w) * xv.w;

    *reinterpret_cast<float4*>(gh + (size_t)gw * HH + c) = h;

    float* dst = xspe + (size_t)node * HH + c;
    atomicAdd(dst + 0, h.x);
    atomicAdd(dst + 1, h.y);
    atomicAdd(dst + 2, h.z);
    atomicAdd(dst + 3, h.w);
}

// ---------------- SGEMM with optional bias+silu epilogue ----------------
// C[M,256] = epi(A[M,K] @ B[K,256] + bias), tile 128x64, 256 threads,
// each thread 8 rows x 4 cols, inner loop uses packed fma.rn.f32x2.
template <int K, bool ACT>
__global__ __launch_bounds__(256)
void gemm_kernel(const float* __restrict__ A,
                 const float* __restrict__ B,
                 const float* __restrict__ bias,
                 float* __restrict__ C) {
    constexpr int BM = 128, BN = 64, BK = 16;
    __shared__ float As[BK][BM + 4];   // +4 pad: conflict-free transposed stores
    __shared__ float Bs[BK][BN];

    const int tid = threadIdx.x;
    const int tx = tid & 15;          // 16 col groups (4 cols each)
    const int ty = tid >> 4;          // 16 row groups (8 rows each)

    const float* Ab = A + (size_t)blockIdx.x * BM * K;
    const float* Bb = B + blockIdx.y * BN;

    unsigned long long acc[4][4];     // [row-pair][col], each holds 2 rows
#pragma unroll
    for (int i = 0; i < 4; i++)
#pragma unroll
        for (int j = 0; j < 4; j++) acc[i][j] = 0ull;

    for (int k0 = 0; k0 < K; k0 += BK) {
        // load A tile 128x16 (512 float4), store transposed
#pragma unroll
        for (int it = 0; it < 2; it++) {
            int q = tid + it * 256;
            int row = q >> 2;
            int c4 = (q & 3) * 4;
            float4 v = *reinterpret_cast<const float4*>(Ab + (size_t)row * K + k0 + c4);
            As[c4 + 0][row] = v.x;
            As[c4 + 1][row] = v.y;
            As[c4 + 2][row] = v.z;
            As[c4 + 3][row] = v.w;
        }
        // load B tile 16x64 (256 float4)
        {
            int row = tid >> 4;
            int c4 = (tid & 15) * 4;
            *reinterpret_cast<float4*>(&Bs[row][c4]) =
                *reinterpret_cast<const float4*>(Bb + (size_t)(k0 + row) * DD + c4);
        }
        __syncthreads();

#pragma unroll
        for (int k = 0; k < BK; k++) {
            // 8 A rows as 4 packed pairs (16B-aligned: (k*(BM+4)+ty*8)*4 is /16)
            ulonglong2 a01 = *reinterpret_cast<const ulonglong2*>(&As[k][ty * 8]);
            ulonglong2 a23 = *reinterpret_cast<const ulonglong2*>(&As[k][ty * 8 + 4]);
            float4 b = *reinterpret_cast<const float4*>(&Bs[k][tx * 4]);
            unsigned long long bb[4] = { pk2(b.x, b.x), pk2(b.y, b.y),
                                         pk2(b.z, b.z), pk2(b.w, b.w) };
#pragma unroll
            for (int j = 0; j < 4; j++) {
                fma2(acc[0][j], a01.x, bb[j]);
                fma2(acc[1][j], a01.y, bb[j]);
                fma2(acc[2][j], a23.x, bb[j]);
                fma2(acc[3][j], a23.y, bb[j]);
            }
        }
        __syncthreads();
    }

    // epilogue
    const int col0 = blockIdx.y * BN + tx * 4;
    float bv[4] = {0.f, 0.f, 0.f, 0.f};
    if (ACT) {
#pragma unroll
        for (int j = 0; j < 4; j++) bv[j] = __ldg(bias + col0 + j);
    }
    float ov[8][4];
#pragma unroll
    for (int rp = 0; rp < 4; rp++)
#pragma unroll
        for (int j = 0; j < 4; j++) {
            float2 f = up2(acc[rp][j]);
            ov[2 * rp + 0][j] = f.x;
            ov[2 * rp + 1][j] = f.y;
        }
#pragma unroll
    for (int r = 0; r < 8; r++) {
        size_t row = (size_t)blockIdx.x * BM + ty * 8 + r;
        float4 o;
        o.x = ov[r][0]; o.y = ov[r][1]; o.z = ov[r][2]; o.w = ov[r][3];
        if (ACT) {
            o.x += bv[0]; o.y += bv[1]; o.z += bv[2]; o.w += bv[3];
            o.x = o.x / (1.f + expf(-o.x));
            o.y = o.y / (1.f + expf(-o.y));
            o.z = o.z / (1.f + expf(-o.z));
            o.w = o.w / (1.f + expf(-o.w));
        }
        *reinterpret_cast<float4*>(C + row * DD + col0) = o;
    }
}

// ---------------- out = t @ w_out  (one warp per edge, D=256 dot) ----------------
__global__ void out_proj_kernel(const float* __restrict__ t,
                                const float* __restrict__ w_out,
                                float* __restrict__ out, int E) {
    int gw = (blockIdx.x * blockDim.x + threadIdx.x) >> 5;
    if (gw >= E) return;
    int lane = threadIdx.x & 31;
    const float4* tr = reinterpret_cast<const float4*>(t + (size_t)gw * DD);
    const float4* w = reinterpret_cast<const float4*>(w_out);
    float s = 0.f;
#pragma unroll
    for (int q = 0; q < 2; q++) {
        float4 a = tr[lane + 32 * q];
        float4 b = __ldg(&w[lane + 32 * q]);
        s += a.x * b.x + a.y * b.y + a.z * b.z + a.w * b.w;
    }
#pragma unroll
    for (int o = 16; o; o >>= 1) s += __shfl_xor_sync(0xffffffffu, s, o);
    if (lane == 0) out[gw] = s;
}

extern "C" void kernel_launch(void* const* d_in, const int* in_sizes, int n_in,
                              void* d_out, int out_size) {
    const float* x     = (const float*)d_in[0];   // [E,128]
    const float* rbf   = (const float*)d_in[1];   // [E,6]
    const int*   idx   = (const int*)  d_in[2];   // [E]
    const float* w_rbf = (const float*)d_in[3];   // [6,128]
    const float* w_up  = (const float*)d_in[4];   // [128,256]
    const float* Ws    = (const float*)d_in[5];   // [3,256,256]
    const float* bs    = (const float*)d_in[6];   // [3,256]
    const float* w_out = (const float*)d_in[7];   // [256,1]

    const int E = in_sizes[2];                    // 400000

    float* out_f = (float*)d_out;
    float* xspe  = out_f;                         // [N,128]
    float* out1  = out_f + (size_t)NN * HH;       // [E]

    float *ph, *pt0, *pt1;
    cudaGetSymbolAddress((void**)&ph,  g_h);
    cudaGetSymbolAddress((void**)&pt0, g_t0);
    cudaGetSymbolAddress((void**)&pt1, g_t1);

    // 1) zero x_spe
    {
        int n4 = (NN * HH) / 4;
        zero_kernel<<<(n4 + 255) / 256, 256>>>((float4*)xspe, n4);
    }
    // 2) h = (rbf@w_rbf)*x, scatter-add, stash h
    {
        int warps = E;
        int blocks = (warps * 32 + 255) / 256;
        h_scatter_kernel<<<blocks, 256>>>(x, rbf, idx, w_rbf, xspe, ph, E);
    }
    // 3) t0 = h @ w_up
    {
        dim3 grid(E / 128, DD / 64);
        gemm_kernel<HH, false><<<grid, 256>>>(ph, w_up, nullptr, pt0);
    }
    // 4) three silu(t@W + b) layers, ping-pong t0/t1
    {
        dim3 grid(E / 128, DD / 64);
        gemm_kernel<DD, true><<<grid, 256>>>(pt0, Ws + 0 * DD * DD, bs + 0 * DD, pt1);
        gemm_kernel<DD, true><<<grid, 256>>>(pt1, Ws + 1 * DD * DD, bs + 1 * DD, pt0);
        gemm_kernel<DD, true><<<grid, 256>>>(pt0, Ws + 2 * DD * DD, bs + 2 * DD, pt1);
    }
    // 5) out = t @ w_out
    {
        int blocks = (E * 32 + 255) / 256;
        out_proj_kernel<<<blocks, 256>>>(pt1, w_out, out1, E);
    }
}

// round 5
// speedup vs baseline: 2.9004x; 2.8989x over previous
#include <cuda_runtime.h>
#include <math.h>
#include <stdint.h>

// Fixed problem shapes
#define EE 400000
#define NN 50000
#define RR 6
#define HH 128
#define DD 256

// Scratch (device globals; no allocation allowed in kernel_launch)
__device__ float g_h [(size_t)EE * HH];                    // [E,128] tf32-rounded
__device__ float g_t0[(size_t)EE * DD];                    // [E,256]
__device__ float g_t1[(size_t)EE * DD];                    // [E,256]
__device__ float g_wr[(size_t)HH * DD + 3 * (size_t)DD * DD]; // rounded weights

// ------------------------------------------------------------------
__device__ __forceinline__ float tf32r(float f) {
    uint32_t u;
    asm("cvt.rna.tf32.f32 %0, %1;" : "=r"(u) : "f"(f));
    return __uint_as_float(u);
}

__device__ __forceinline__ uint32_t smem_u32(const void* p) {
    uint32_t a;
    asm("{ .reg .u64 t; cvta.to.shared.u64 t, %1; cvt.u32.u64 %0, t; }"
        : "=r"(a) : "l"(p));
    return a;
}

__device__ __forceinline__ void mma_tf32(float* c, const uint32_t* a,
                                         const uint32_t* b) {
    asm volatile(
        "mma.sync.aligned.m16n8k8.row.col.f32.tf32.tf32.f32 "
        "{%0,%1,%2,%3}, {%4,%5,%6,%7}, {%8,%9}, {%0,%1,%2,%3};"
        : "+f"(c[0]), "+f"(c[1]), "+f"(c[2]), "+f"(c[3])
        : "r"(a[0]), "r"(a[1]), "r"(a[2]), "r"(a[3]), "r"(b[0]), "r"(b[1]));
}

__device__ __forceinline__ float silu(float v) {
    return __fdividef(v, 1.f + __expf(-v));
}

// ------------------------------------------------------------------
__global__ void zero_kernel(float4* p, int n4) {
    int i = blockIdx.x * blockDim.x + threadIdx.x;
    if (i < n4) p[i] = make_float4(0.f, 0.f, 0.f, 0.f);
}

// round weights (w_up then Ws) to tf32 into g_wr
__global__ void round_weights(const float* __restrict__ wup,
                              const float* __restrict__ Ws,
                              float* __restrict__ dst) {
    int i = blockIdx.x * blockDim.x + threadIdx.x;
    const int n1 = HH * DD;
    const int tot = n1 + 3 * DD * DD;
    if (i < n1) dst[i] = tf32r(wup[i]);
    else if (i < tot) dst[i] = tf32r(Ws[i - n1]);
}

// h = (rbf @ w_rbf) * x ; scatter-add fp32 into x_spe ; store tf32(h)
__global__ void h_scatter_kernel(const float* __restrict__ x,
                                 const float* __restrict__ rbf,
                                 const int*   __restrict__ idx,
                                 const float* __restrict__ w_rbf,
                                 float* __restrict__ xspe,
                                 float* __restrict__ gh,
                                 int E) {
    int gw = (blockIdx.x * blockDim.x + threadIdx.x) >> 5;
    if (gw >= E) return;
    int lane = threadIdx.x & 31;
    int c = lane * 4;

    const float* rb = rbf + (size_t)gw * RR;
    float r0 = __ldg(rb + 0), r1 = __ldg(rb + 1), r2 = __ldg(rb + 2);
    float r3 = __ldg(rb + 3), r4 = __ldg(rb + 4), r5 = __ldg(rb + 5);
    int node = __ldg(idx + gw);

    float4 xv = *reinterpret_cast<const float4*>(x + (size_t)gw * HH + c);
    float4 w0 = *reinterpret_cast<const float4*>(w_rbf + 0 * HH + c);
    float4 w1 = *reinterpret_cast<const float4*>(w_rbf + 1 * HH + c);
    float4 w2 = *reinterpret_cast<const float4*>(w_rbf + 2 * HH + c);
    float4 w3 = *reinterpret_cast<const float4*>(w_rbf + 3 * HH + c);
    float4 w4 = *reinterpret_cast<const float4*>(w_rbf + 4 * HH + c);
    float4 w5 = *reinterpret_cast<const float4*>(w_rbf + 5 * HH + c);

    float4 h;
    h.x = (r0*w0.x + r1*w1.x + r2*w2.x + r3*w3.x + r4*w4.x + r5*w5.x) * xv.x;
    h.y = (r0*w0.y + r1*w1.y + r2*w2.y + r3*w3.y + r4*w4.y + r5*w5.y) * xv.y;
    h.z = (r0*w0.z + r1*w1.z + r2*w2.z + r3*w3.z + r4*w4.z + r5*w5.z) * xv.z;
    h.w = (r0*w0.w + r1*w1.w + r2*w2.w + r3*w3.w + r4*w4.w + r5*w5.w) * xv.w;

    float4 hr;
    hr.x = tf32r(h.x); hr.y = tf32r(h.y); hr.z = tf32r(h.z); hr.w = tf32r(h.w);
    *reinterpret_cast<float4*>(gh + (size_t)gw * HH + c) = hr;

    float* dst = xspe + (size_t)node * HH + c;
    atomicAdd(dst + 0, h.x);
    atomicAdd(dst + 1, h.y);
    atomicAdd(dst + 2, h.z);
    atomicAdd(dst + 3, h.w);
}

// ------------------------------------------------------------------
// tf32 mma.sync GEMM: C[E,256] = epi(A[E,KTOT] @ B[KTOT,256])
// CTA tile 128x128xBK32, 8 warps (2m x 4n), warp tile 64x32.
// A,B expected pre-rounded to tf32. Double-buffered cp.async.
// LAST: fuse out[row] += sum_n silu(acc+bias)[row,n] * wout[n] (atomicAdd).
// ------------------------------------------------------------------
#define GEMM_SMEM (17920 * 4)   // As 2*4608 + Bs 2*4352 floats = 71680 B

template<int KTOT, bool ACT, bool LAST>
__global__ __launch_bounds__(256, 2)
void gemm_mma(const float* __restrict__ A, const float* __restrict__ B,
              const float* __restrict__ bias, const float* __restrict__ wout,
              float* __restrict__ C, float* __restrict__ outv)
{
    constexpr int BK = 32, ASTR = 36, BSTR = 136;
    constexpr int NCH = KTOT / BK;
    constexpr int A_FL = 4608, B0_FL = 9216, B_FL = 4352;

    extern __shared__ float sm[];
    const uint32_t sb = smem_u32(sm);

    const int tid  = threadIdx.x;
    const int warp = tid >> 5, lane = tid & 31;
    const int g = lane >> 2, t = lane & 3;
    const int wm = warp & 1, wn = warp >> 1;

    const float* Ab = A + (size_t)blockIdx.x * 128 * KTOT;
    const float* Bb = B + blockIdx.y * 128;

    float acc[4][4][4];
#pragma unroll
    for (int i = 0; i < 4; i++)
#pragma unroll
        for (int j = 0; j < 4; j++)
#pragma unroll
            for (int q = 0; q < 4; q++) acc[i][j][q] = 0.f;

    auto load_chunk = [&](int c, int st) {
        const int k0 = c * BK;
        // A: 128 rows x 32 cols
        uint32_t ad = sb + (uint32_t)st * (A_FL * 4);
#pragma unroll
        for (int it = 0; it < 4; it++) {
            int q = tid + it * 256;
            int row = q >> 3, c4 = (q & 7) << 2;
            const float* src = Ab + (size_t)row * KTOT + k0 + c4;
            uint32_t dst = ad + (uint32_t)(row * ASTR + c4) * 4;
            asm volatile("cp.async.cg.shared.global [%0], [%1], 16;"
                         :: "r"(dst), "l"(src));
        }
        // B: 32 rows x 128 cols
        uint32_t bd = sb + (uint32_t)(B0_FL + st * B_FL) * 4;
#pragma unroll
        for (int it = 0; it < 4; it++) {
            int q = tid + it * 256;
            int row = q >> 5, c4 = (q & 31) << 2;
            const float* src = Bb + (size_t)(k0 + row) * DD + c4;
            uint32_t dst = bd + (uint32_t)(row * BSTR + c4) * 4;
            asm volatile("cp.async.cg.shared.global [%0], [%1], 16;"
                         :: "r"(dst), "l"(src));
        }
        asm volatile("cp.async.commit_group;" ::: "memory");
    };

    auto compute = [&](int st) {
        const uint32_t* as = reinterpret_cast<const uint32_t*>(sm + st * A_FL);
        const uint32_t* bs = reinterpret_cast<const uint32_t*>(sm + B0_FL + st * B_FL);
#pragma unroll
        for (int ks = 0; ks < 4; ks++) {
            const int k = ks * 8;
            uint32_t af[4][4], bf[4][2];
#pragma unroll
            for (int mf = 0; mf < 4; mf++) {
                int r0 = wm * 64 + mf * 16 + g;
                af[mf][0] = as[r0 * ASTR + k + t];
                af[mf][1] = as[(r0 + 8) * ASTR + k + t];
                af[mf][2] = as[r0 * ASTR + k + 4 + t];
                af[mf][3] = as[(r0 + 8) * ASTR + k + 4 + t];
            }
#pragma unroll
            for (int nf = 0; nf < 4; nf++) {
                int c0 = wn * 32 + nf * 8 + g;
                bf[nf][0] = bs[(k + t) * BSTR + c0];
                bf[nf][1] = bs[(k + 4 + t) * BSTR + c0];
            }
#pragma unroll
            for (int mf = 0; mf < 4; mf++)
#pragma unroll
                for (int nf = 0; nf < 4; nf++)
                    mma_tf32(acc[mf][nf], af[mf], bf[nf]);
        }
    };

    load_chunk(0, 0);
#pragma unroll 1
    for (int c = 0; c < NCH; c++) {
        if (c + 1 < NCH) {
            load_chunk(c + 1, (c + 1) & 1);
            asm volatile("cp.async.wait_group 1;" ::: "memory");
        } else {
            asm volatile("cp.async.wait_group 0;" ::: "memory");
        }
        __syncthreads();
        compute(c & 1);
        __syncthreads();
    }

    // ---------------- epilogue ----------------
    const int rowb = blockIdx.x * 128 + wm * 64;
    const int colb = blockIdx.y * 128 + wn * 32;

    if (!LAST) {
#pragma unroll
        for (int mf = 0; mf < 4; mf++) {
#pragma unroll
            for (int nf = 0; nf < 4; nf++) {
                int r0 = rowb + mf * 16 + g;
                int cc = colb + nf * 8 + 2 * t;
                float v0 = acc[mf][nf][0], v1 = acc[mf][nf][1];
                float v2 = acc[mf][nf][2], v3 = acc[mf][nf][3];
                if (ACT) {
                    float b0 = __ldg(bias + cc), b1 = __ldg(bias + cc + 1);
                    v0 = silu(v0 + b0); v1 = silu(v1 + b1);
                    v2 = silu(v2 + b0); v3 = silu(v3 + b1);
                }
                float2 o0 = make_float2(tf32r(v0), tf32r(v1));
                float2 o1 = make_float2(tf32r(v2), tf32r(v3));
                *reinterpret_cast<float2*>(C + (size_t)r0 * DD + cc) = o0;
                *reinterpret_cast<float2*>(C + (size_t)(r0 + 8) * DD + cc) = o1;
            }
        }
    } else {
        float s0[4], s1[4];
#pragma unroll
        for (int mf = 0; mf < 4; mf++) { s0[mf] = 0.f; s1[mf] = 0.f; }
#pragma unroll
        for (int mf = 0; mf < 4; mf++) {
#pragma unroll
            for (int nf = 0; nf < 4; nf++) {
                int cc = colb + nf * 8 + 2 * t;
                float b0 = __ldg(bias + cc), b1 = __ldg(bias + cc + 1);
                float w0 = __ldg(wout + cc), w1 = __ldg(wout + cc + 1);
                float v0 = silu(acc[mf][nf][0] + b0);
                float v1 = silu(acc[mf][nf][1] + b1);
                float v2 = silu(acc[mf][nf][2] + b0);
                float v3 = silu(acc[mf][nf][3] + b1);
                s0[mf] += v0 * w0 + v1 * w1;
                s1[mf] += v2 * w0 + v3 * w1;
            }
        }
        // quad reduce (lanes sharing the same row: t = 0..3)
#pragma unroll
        for (int mf = 0; mf < 4; mf++) {
            s0[mf] += __shfl_xor_sync(0xffffffffu, s0[mf], 1);
            s0[mf] += __shfl_xor_sync(0xffffffffu, s0[mf], 2);
            s1[mf] += __shfl_xor_sync(0xffffffffu, s1[mf], 1);
            s1[mf] += __shfl_xor_sync(0xffffffffu, s1[mf], 2);
        }
        __syncthreads();               // smem tiles no longer needed
        float* red = sm;               // red[row_local * 4 + wn]
        if (t == 0) {
#pragma unroll
            for (int mf = 0; mf < 4; mf++) {
                int rl = wm * 64 + mf * 16 + g;
                red[rl * 4 + wn] = s0[mf];
                red[(rl + 8) * 4 + wn] = s1[mf];
            }
        }
        __syncthreads();
        if (tid < 128) {
            float s = red[tid * 4] + red[tid * 4 + 1]
                    + red[tid * 4 + 2] + red[tid * 4 + 3];
            atomicAdd(outv + (size_t)blockIdx.x * 128 + tid, s);
        }
    }
}

// ------------------------------------------------------------------
extern "C" void kernel_launch(void* const* d_in, const int* in_sizes, int n_in,
                              void* d_out, int out_size) {
    const float* x     = (const float*)d_in[0];   // [E,128]
    const float* rbf   = (const float*)d_in[1];   // [E,6]
    const int*   idx   = (const int*)  d_in[2];   // [E]
    const float* w_rbf = (const float*)d_in[3];   // [6,128]
    const float* w_up  = (const float*)d_in[4];   // [128,256]
    const float* Ws    = (const float*)d_in[5];   // [3,256,256]
    const float* bs    = (const float*)d_in[6];   // [3,256]
    const float* w_out = (const float*)d_in[7];   // [256,1]

    const int E = in_sizes[2];                    // 400000

    float* out_f = (float*)d_out;
    float* xspe  = out_f;                         // [N,128]
    float* out1  = out_f + (size_t)NN * HH;       // [E]

    float *ph, *pt0, *pt1, *pwr;
    cudaGetSymbolAddress((void**)&ph,  g_h);
    cudaGetSymbolAddress((void**)&pt0, g_t0);
    cudaGetSymbolAddress((void**)&pt1, g_t1);
    cudaGetSymbolAddress((void**)&pwr, g_wr);

    cudaFuncSetAttribute(gemm_mma<128, false, false>,
                         cudaFuncAttributeMaxDynamicSharedMemorySize, GEMM_SMEM);
    cudaFuncSetAttribute(gemm_mma<256, true, false>,
                         cudaFuncAttributeMaxDynamicSharedMemorySize, GEMM_SMEM);
    cudaFuncSetAttribute(gemm_mma<256, true, true>,
                         cudaFuncAttributeMaxDynamicSharedMemorySize, GEMM_SMEM);

    // 0) round weights to tf32 (RNA) once per launch
    {
        int tot = HH * DD + 3 * DD * DD;
        round_weights<<<(tot + 255) / 256, 256>>>(w_up, Ws, pwr);
    }
    // 1) zero the whole output (x_spe needs zeros; out1 accumulated atomically)
    {
        int n4 = (NN * HH + EE) / 4;
        zero_kernel<<<(n4 + 255) / 256, 256>>>((float4*)out_f, n4);
    }
    // 2) h = (rbf@w_rbf)*x, fp32 scatter-add, stash tf32(h)
    {
        int blocks = (E * 32 + 255) / 256;
        h_scatter_kernel<<<blocks, 256>>>(x, rbf, idx, w_rbf, xspe, ph, E);
    }
    // 3) GEMM tower on tensor cores (tf32 mma.sync); last layer fuses @w_out
    {
        dim3 grid(E / 128, 2);
        const float* W0 = pwr;                    // [128,256]
        const float* W1 = pwr + HH * DD;          // [256,256] x3
        gemm_mma<128, false, false><<<grid, 256, GEMM_SMEM>>>(
            ph, W0, nullptr, nullptr, pt0, nullptr);
        gemm_mma<256, true, false><<<grid, 256, GEMM_SMEM>>>(
            pt0, W1 + 0 * DD * DD, bs + 0 * DD, nullptr, pt1, nullptr);
        gemm_mma<256, true, false><<<grid, 256, GEMM_SMEM>>>(
            pt1, W1 + 1 * DD * DD, bs + 1 * DD, nullptr, pt0, nullptr);
        gemm_mma<256, true, true><<<grid, 256, GEMM_SMEM>>>(
            pt0, W1 + 2 * DD * DD, bs + 2 * DD, w_out, nullptr, out1);
    }
}